// round 2
// baseline (speedup 1.0000x reference)
#include <cuda_runtime.h>

// Problem constants
#define B_ 2048
#define C_ 50000
#define D_ 128
#define BM 128
#define BN 128
#define BK 32
#define TM 8
#define TN 8
#define NT ((C_ + BN - 1) / BN)   /* 391 */

// Scratch (static device arrays: allocation-free per harness rules)
__device__ float g_invx[B_];
__device__ float g_invw[C_];
__device__ float g_ps1[(size_t)B_ * NT];
__device__ float g_ps2[(size_t)B_ * NT];
__device__ float g_rowloss[B_];
__device__ float g_invs1[B_];

// exp(x) for x in ~[-1.1, 1.1] : degree-8 Taylor, abs err ~5e-6.
// Avoids MUFU (rt 8/SMSP) which would dominate at 102M evaluations.
__device__ __forceinline__ float exp_poly(float x) {
    float p = 2.4801587e-5f;
    p = fmaf(p, x, 1.9841270e-4f);
    p = fmaf(p, x, 1.3888889e-3f);
    p = fmaf(p, x, 8.3333333e-3f);
    p = fmaf(p, x, 4.1666668e-2f);
    p = fmaf(p, x, 1.6666667e-1f);
    p = fmaf(p, x, 0.5f);
    p = fmaf(p, x, 1.0f);
    p = fmaf(p, x, 1.0f);
    return p;
}

// e^20 via 5 multiplies (exp(20*wf) = exp(wf)^20)
__device__ __forceinline__ float pow20(float e) {
    float t2 = e * e;
    float t4 = t2 * t2;
    float t8 = t4 * t4;
    float t16 = t8 * t8;
    return t16 * t4;
}

// 1 / max(||row||, 1e-12) ; one warp per row, D=128 (4 floats/lane)
__global__ void rownorm_kernel(const float* __restrict__ v, int nrows, int mode) {
    int row = blockIdx.x * 8 + (threadIdx.x >> 5);
    if (row >= nrows) return;
    int lane = threadIdx.x & 31;
    float4 q = *(const float4*)(v + (size_t)row * D_ + lane * 4);
    float s = q.x * q.x + q.y * q.y + q.z * q.z + q.w * q.w;
#pragma unroll
    for (int o = 16; o; o >>= 1) s += __shfl_xor_sync(0xffffffffu, s, o);
    if (lane == 0) {
        float r = 1.0f / fmaxf(sqrtf(s), 1e-12f);
        if (mode) g_invw[row] = r;
        else      g_invx[row] = r;
    }
}

// GEMM: wf = (x . W_j) * invx * invw + b ; writes exp(wf) to out,
// accumulates per-row sum(exp(wf)) and sum(exp(20*wf)) partials per N-tile.
// Inner loop uses packed fma.rn.f32x2 (full-rate fma pipe on sm_103a).
__global__ __launch_bounds__(256, 2)
void gemm_kernel(const float* __restrict__ X, const float* __restrict__ Wt,
                 const float* __restrict__ bias, float* __restrict__ out) {
    __shared__ __align__(16) float As[BK][BM];
    __shared__ __align__(16) float Bs[BK][BN];
    __shared__ float s1sh[BM], s2sh[BM];

    const int bx = blockIdx.x;           // N tile (0..390)
    const int by = blockIdx.y;           // M tile (0..15)
    const int tid = threadIdx.x;
    const int tx = tid & 15, ty = tid >> 4;
    const int rowBase = by * BM, colBase = bx * BN;

    // acc2[p][j] : packed rows (2p, 2p+1) for column j
    unsigned long long acc2[4][TN];
#pragma unroll
    for (int p = 0; p < 4; p++)
#pragma unroll
        for (int j = 0; j < TN; j++) acc2[p][j] = 0ull;

    for (int k0 = 0; k0 < D_; k0 += BK) {
        // Load A tile (128x32) transposed -> As[k][m]
#pragma unroll
        for (int i = 0; i < 4; i++) {
            int f = tid + i * 256;
            int m = f >> 3, kq = f & 7;
            float4 v = *(const float4*)(X + (size_t)(rowBase + m) * D_ + k0 + kq * 4);
            As[kq * 4 + 0][m] = v.x; As[kq * 4 + 1][m] = v.y;
            As[kq * 4 + 2][m] = v.z; As[kq * 4 + 3][m] = v.w;
        }
        // Load W tile (128x32) transposed -> Bs[k][j], zero-pad class tail
#pragma unroll
        for (int i = 0; i < 4; i++) {
            int f = tid + i * 256;
            int j = f >> 3, kq = f & 7;
            int gj = colBase + j;
            float4 v = make_float4(0.f, 0.f, 0.f, 0.f);
            if (gj < C_) v = *(const float4*)(Wt + (size_t)gj * D_ + k0 + kq * 4);
            Bs[kq * 4 + 0][j] = v.x; Bs[kq * 4 + 1][j] = v.y;
            Bs[kq * 4 + 2][j] = v.z; Bs[kq * 4 + 3][j] = v.w;
        }
        __syncthreads();
#pragma unroll
        for (int k = 0; k < BK; k++) {
            unsigned long long a2[4];
#pragma unroll
            for (int p = 0; p < 4; p++)
                a2[p] = *(const unsigned long long*)&As[k][ty * TM + 2 * p];
            float4 b0 = *(const float4*)&Bs[k][tx * TN];
            float4 b1 = *(const float4*)&Bs[k][tx * TN + 4];
            float br[8] = {b0.x, b0.y, b0.z, b0.w, b1.x, b1.y, b1.z, b1.w};
#pragma unroll
            for (int j = 0; j < TN; j++) {
                unsigned long long bd;
                asm("mov.b64 %0, {%1, %2};"
                    : "=l"(bd) : "r"(__float_as_uint(br[j])), "r"(__float_as_uint(br[j])));
#pragma unroll
                for (int p = 0; p < 4; p++)
                    asm("fma.rn.f32x2 %0, %1, %2, %0;"
                        : "+l"(acc2[p][j]) : "l"(a2[p]), "l"(bd));
            }
        }
        __syncthreads();
    }

    // ---- Epilogue ----
    // C_ % TN == 0, so each thread's 8-column group is entirely valid or entirely not.
    const bool colValid = (colBase + tx * TN) < C_;
    float invw8[TN], b8[TN];
#pragma unroll
    for (int j = 0; j < TN; j++) {
        int gj = colBase + tx * TN + j;
        invw8[j] = colValid ? g_invw[gj] : 0.f;
        b8[j]    = colValid ? bias[gj]  : 0.f;
    }
    float accf[TM][TN];
#pragma unroll
    for (int p = 0; p < 4; p++)
#pragma unroll
        for (int j = 0; j < TN; j++) {
            unsigned int lo, hi;
            asm("mov.b64 {%0, %1}, %2;" : "=r"(lo), "=r"(hi) : "l"(acc2[p][j]));
            accf[2 * p + 0][j] = __uint_as_float(lo);
            accf[2 * p + 1][j] = __uint_as_float(hi);
        }
    float invxr[TM];
#pragma unroll
    for (int i = 0; i < TM; i++) invxr[i] = g_invx[rowBase + ty * TM + i];

    float p1[TM], p2[TM];
#pragma unroll
    for (int i = 0; i < TM; i++) { p1[i] = 0.f; p2[i] = 0.f; }

#pragma unroll
    for (int i = 0; i < TM; i++) {
        float ev[TN];
#pragma unroll
        for (int j = 0; j < TN; j++) {
            float wf = fmaf(accf[i][j] * invxr[i], invw8[j], b8[j]);
            float e1 = exp_poly(wf);
            ev[j] = e1;
            if (colValid) {
                p1[i] += e1;
                p2[i] += pow20(e1);
            }
        }
        if (colValid) {
            size_t off = (size_t)(rowBase + ty * TM + i) * C_ + colBase + tx * TN;
            *(float4*)(out + off)     = make_float4(ev[0], ev[1], ev[2], ev[3]);
            *(float4*)(out + off + 4) = make_float4(ev[4], ev[5], ev[6], ev[7]);
        }
    }

    // Reduce p1/p2 across the 16 tx lanes (stays inside half-warp), store per-tile partials
#pragma unroll
    for (int i = 0; i < TM; i++) {
        float v1 = p1[i], v2 = p2[i];
#pragma unroll
        for (int o = 8; o; o >>= 1) {
            v1 += __shfl_xor_sync(0xffffffffu, v1, o);
            v2 += __shfl_xor_sync(0xffffffffu, v2, o);
        }
        if (tx == 0) { s1sh[ty * TM + i] = v1; s2sh[ty * TM + i] = v2; }
    }
    __syncthreads();
    if (tid < BM) {
        g_ps1[(size_t)(rowBase + tid) * NT + bx] = s1sh[tid];
        g_ps2[(size_t)(rowBase + tid) * NT + bx] = s2sh[tid];
    }
}

__device__ __forceinline__ float blkred128(float v, float* sh) {
    int t = threadIdx.x;
    sh[t] = v;
    __syncthreads();
#pragma unroll
    for (int o = 64; o > 0; o >>= 1) {
        if (t < o) sh[t] += sh[t + o];
        __syncthreads();
    }
    float r = sh[0];
    __syncthreads();
    return r;
}

// Per-row: reduce partials, compute label logit + margin, row loss term, 1/sum(exp)
__global__ void rowfinal_kernel(const float* __restrict__ X, const float* __restrict__ Wt,
                                const float* __restrict__ bias, const int* __restrict__ labels) {
    __shared__ float sh[128];
    int row = blockIdx.x, t = threadIdx.x;

    float s1 = 0.f, s2 = 0.f;
    for (int j = t; j < NT; j += 128) {
        s1 += g_ps1[(size_t)row * NT + j];
        s2 += g_ps2[(size_t)row * NT + j];
    }
    int lab = labels[row];
    float d = X[(size_t)row * D_ + t] * Wt[(size_t)lab * D_ + t];

    s1 = blkred128(s1, sh);
    s2 = blkred128(s2, sh);
    d  = blkred128(d, sh);

    if (t == 0) {
        float wl = fmaf(d * g_invx[row], g_invw[lab], bias[lab]);
        float c = fminf(fmaxf(wl, -1.f + 1e-7f), 1.f - 1e-7f);
        // cos(acos(c) + M) = c*cos(M) - sqrt(1-c^2)*sin(M),  M = 0.1
        float cosm = c * 0.9950041652780258f
                   - sqrtf(fmaxf(1.f - c * c, 0.f)) * 0.09983341664682815f;
        // same poly path as GEMM so the label term cancels exactly
        float e2l = pow20(exp_poly(wl));
        float e2m = pow20(exp_poly(cosm));
        float s2p = s2 - e2l + e2m;
        g_rowloss[row] = logf(s2p) - 20.f * cosm;   // -logp[label]
        g_invs1[row] = 1.f / s1;
    }
}

__global__ void loss_kernel(float* __restrict__ out, int out_size) {
    __shared__ float sh[256];
    int t = threadIdx.x;
    float s = 0.f;
    for (int i = t; i < B_; i += 256) s += g_rowloss[i];
    sh[t] = s;
    __syncthreads();
#pragma unroll
    for (int o = 128; o > 0; o >>= 1) {
        if (t < o) sh[t] += sh[t + o];
        __syncthreads();
    }
    if (t == 0) out[out_size - 1] = sh[0] / (float)B_;
}

// prediction = exp(wf) / sum(exp(wf)) ; float4 in-place scale
__global__ void scale_kernel(float* __restrict__ out) {
    int row = blockIdx.y;
    float inv = g_invs1[row];
    int i = blockIdx.x * blockDim.x + threadIdx.x;   // float4 index, C_/4 = 12500
    if (i < C_ / 4) {
        float4* p = (float4*)(out + (size_t)row * C_);
        float4 v = p[i];
        v.x *= inv; v.y *= inv; v.z *= inv; v.w *= inv;
        p[i] = v;
    }
}

extern "C" void kernel_launch(void* const* d_in, const int* in_sizes, int n_in,
                              void* d_out, int out_size) {
    const float* X     = (const float*)d_in[0];   // [2048, 128]
    const float* W     = (const float*)d_in[1];   // [50000, 128]
    const float* bias  = (const float*)d_in[2];   // [50000]
    const int*   labels = (const int*)d_in[3];    // [2048]
    float* out = (float*)d_out;                   // [2048*50000 + 1]
    (void)in_sizes; (void)n_in;

    rownorm_kernel<<<B_ / 8, 256>>>(X, B_, 0);
    rownorm_kernel<<<(C_ + 7) / 8, 256>>>(W, C_, 1);
    gemm_kernel<<<dim3(NT, B_ / BM), 256>>>(X, W, bias, out);
    rowfinal_kernel<<<B_, 128>>>(X, W, bias, labels);
    loss_kernel<<<1, 256>>>(out, out_size);
    scale_kernel<<<dim3((C_ / 4 + 255) / 256, B_), 256>>>(out);
}

// round 5
// speedup vs baseline: 2.0921x; 2.0921x over previous
#include <cuda_runtime.h>
#include <cstdint>

// Problem constants
#define B_ 2048
#define C_ 50000
#define D_ 128
#define BM 128
#define BN 128
#define NT ((C_ + BN - 1) / BN)   /* 391 */
#define LDA 132                   /* padded smem row stride (floats) */

// Scratch (static device arrays: allocation-free per harness rules)
__device__ float g_invx[B_];
__device__ float g_invw[C_];
__device__ float g_ps1[(size_t)B_ * NT];
__device__ float g_ps2[(size_t)B_ * NT];
__device__ float g_rowloss[B_];
__device__ float g_invs1[B_];

// ---------------- helpers ----------------
__device__ __forceinline__ uint32_t smem_u32(const void* p) {
    uint32_t a;
    asm("{ .reg .u64 t; cvta.to.shared.u64 t, %1; cvt.u32.u64 %0, t; }"
        : "=r"(a) : "l"(p));
    return a;
}

__device__ __forceinline__ void cpasync16(uint32_t dst, const void* src, int sz) {
    asm volatile("cp.async.cg.shared.global [%0], [%1], 16, %2;"
                 :: "r"(dst), "l"(src), "r"(sz));
}

// tf32 mma m16n8k8 (portable sm_80+ ISA; compiles on plain sm_103 target)
__device__ __forceinline__ void mma_tf32(float* c, const uint32_t* a, const uint32_t* b) {
    asm volatile(
        "mma.sync.aligned.m16n8k8.row.col.f32.tf32.tf32.f32 "
        "{%0,%1,%2,%3}, {%4,%5,%6,%7}, {%8,%9}, {%0,%1,%2,%3};"
        : "+f"(c[0]), "+f"(c[1]), "+f"(c[2]), "+f"(c[3])
        : "r"(a[0]), "r"(a[1]), "r"(a[2]), "r"(a[3]), "r"(b[0]), "r"(b[1]));
}

// e^20 via 5 multiplies
__device__ __forceinline__ float pow20(float e) {
    float t2 = e * e;
    float t4 = t2 * t2;
    float t8 = t4 * t4;
    float t16 = t8 * t8;
    return t16 * t4;
}

// ---------------- kernels ----------------

// 1 / max(||row||, 1e-12) ; one warp per row, D=128
__global__ void rownorm_kernel(const float* __restrict__ v, int nrows, int mode) {
    int row = blockIdx.x * 8 + (threadIdx.x >> 5);
    if (row >= nrows) return;
    int lane = threadIdx.x & 31;
    float4 q = *(const float4*)(v + (size_t)row * D_ + lane * 4);
    float s = q.x * q.x + q.y * q.y + q.z * q.z + q.w * q.w;
#pragma unroll
    for (int o = 16; o; o >>= 1) s += __shfl_xor_sync(0xffffffffu, s, o);
    if (lane == 0) {
        float r = 1.0f / fmaxf(sqrtf(s), 1e-12f);
        if (mode) g_invw[row] = r;
        else      g_invx[row] = r;
    }
}

// Tensor-core (mma.sync tf32) GEMM with fused softmax-numerator epilogue:
// acc = X_tile @ W_tile^T ; wf = acc*invw*invx + bias ; out = exp(wf);
// also writes per-(row, N-tile) partial sums of exp(wf) and exp(wf)^20.
// Dynamic smem (floats):
//   As[128*132], Bs[128*132], invw_s[128], bias_s[128], invx_s[128],
//   s1w[4][128], s2w[4][128]
__global__ __launch_bounds__(256, 1)
void gemm_tc_kernel(const float* __restrict__ X, const float* __restrict__ Wt,
                    const float* __restrict__ bias, float* __restrict__ out) {
    extern __shared__ __align__(16) float sm[];
    float* As     = sm;                    // 128*132
    float* Bs     = sm + 128 * LDA;        // 128*132
    float* invw_s = sm + 2 * 128 * LDA;
    float* bias_s = invw_s + 128;
    float* invx_s = bias_s + 128;
    float* s1w    = invx_s + 128;          // [4][128]
    float* s2w    = s1w + 512;             // [4][128]

    const int tid  = threadIdx.x;
    const int w    = tid >> 5;
    const int lane = tid & 31;
    const int g    = lane >> 2;            // 0..7
    const int q    = lane & 3;             // 0..3
    const int warp_m = w >> 2;             // 0..1
    const int warp_n = w & 3;              // 0..3
    const int bx = blockIdx.x;             // N tile
    const int by = blockIdx.y;             // M tile
    const int rowBase = by * BM, colBase = bx * BN;

    const uint32_t smA = smem_u32(As);
    const uint32_t smB = smem_u32(Bs);

    // Async tile loads: 128 rows x 32 float4 each
    const float* Abase = X + (size_t)rowBase * D_;
#pragma unroll
    for (int i = 0; i < 16; i++) {
        int flat = tid + i * 256;           // [0, 4096)
        int r = flat >> 5, c4 = flat & 31;
        cpasync16(smA + (uint32_t)(r * LDA + c4 * 4) * 4u,
                  Abase + (size_t)r * D_ + c4 * 4, 16);
    }
#pragma unroll
    for (int i = 0; i < 16; i++) {
        int flat = tid + i * 256;
        int r = flat >> 5, c4 = flat & 31;
        int gj = colBase + r;
        int ok = (gj < C_);
        cpasync16(smB + (uint32_t)(r * LDA + c4 * 4) * 4u,
                  Wt + (size_t)(ok ? gj : 0) * D_ + c4 * 4, ok ? 16 : 0);
    }
    asm volatile("cp.async.commit_group;" ::: "memory");

    // Per-column invw/bias, per-row invx
    if (tid < 128) {
        int gj = colBase + tid;
        invw_s[tid] = (gj < C_) ? g_invw[gj] : 0.f;
        bias_s[tid] = (gj < C_) ? bias[gj]  : 0.f;
        invx_s[tid] = g_invx[rowBase + tid];
    }
    asm volatile("cp.async.wait_group 0;" ::: "memory");
    __syncthreads();

    // MMA mainloop: warp tile 64(M) x 32(N) = 4x4 m16n8k8 tiles, K in 16 steps
    float acc[4][4][4];
#pragma unroll
    for (int mt = 0; mt < 4; mt++)
#pragma unroll
        for (int nt = 0; nt < 4; nt++)
#pragma unroll
            for (int r = 0; r < 4; r++) acc[mt][nt][r] = 0.f;

    const float* Aw = As + (warp_m * 64 + g) * LDA + q;
    const float* Bw = Bs + (warp_n * 32 + g) * LDA + q;

    for (int ks = 0; ks < 16; ks++) {
        const int kb = ks * 8;
        uint32_t af[4][4], bf[4][2];
#pragma unroll
        for (int mt = 0; mt < 4; mt++) {
            const float* ap = Aw + mt * 16 * LDA + kb;
            af[mt][0] = __float_as_uint(ap[0]);
            af[mt][1] = __float_as_uint(ap[8 * LDA]);
            af[mt][2] = __float_as_uint(ap[4]);
            af[mt][3] = __float_as_uint(ap[8 * LDA + 4]);
        }
#pragma unroll
        for (int nt = 0; nt < 4; nt++) {
            const float* bp = Bw + nt * 8 * LDA + kb;
            bf[nt][0] = __float_as_uint(bp[0]);
            bf[nt][1] = __float_as_uint(bp[4]);
        }
#pragma unroll
        for (int mt = 0; mt < 4; mt++)
#pragma unroll
            for (int nt = 0; nt < 4; nt++)
                mma_tf32(acc[mt][nt], af[mt], bf[nt]);
    }

    // Epilogue: wf -> exp -> direct STG.64 (c0/c1 are adjacent columns),
    // accumulate per-row partial sums.
    float p1r[4][2], p2r[4][2];
#pragma unroll
    for (int mt = 0; mt < 4; mt++) {
        p1r[mt][0] = p1r[mt][1] = 0.f;
        p2r[mt][0] = p2r[mt][1] = 0.f;
    }

#pragma unroll
    for (int mt = 0; mt < 4; mt++) {
        const int lr0 = warp_m * 64 + mt * 16 + g;
        const float inx0 = invx_s[lr0];
        const float inx1 = invx_s[lr0 + 8];
        float* out0 = out + (size_t)(rowBase + lr0) * C_ + colBase;
        float* out1 = out + (size_t)(rowBase + lr0 + 8) * C_ + colBase;
#pragma unroll
        for (int nt = 0; nt < 4; nt++) {
            const int lc = warp_n * 32 + nt * 8 + 2 * q;
            const bool valid = (colBase + warp_n * 32 + nt * 8) < C_;
            const float iw0 = invw_s[lc],     iw1 = invw_s[lc + 1];
            const float bs0 = bias_s[lc],     bs1 = bias_s[lc + 1];
            float e00 = __expf(fmaf(acc[mt][nt][0] * iw0, inx0, bs0));
            float e01 = __expf(fmaf(acc[mt][nt][1] * iw1, inx0, bs1));
            float e10 = __expf(fmaf(acc[mt][nt][2] * iw0, inx1, bs0));
            float e11 = __expf(fmaf(acc[mt][nt][3] * iw1, inx1, bs1));
            if (valid) {
                *(float2*)(out0 + lc) = make_float2(e00, e01);
                *(float2*)(out1 + lc) = make_float2(e10, e11);
                p1r[mt][0] += e00 + e01;
                p1r[mt][1] += e10 + e11;
                p2r[mt][0] += pow20(e00) + pow20(e01);
                p2r[mt][1] += pow20(e10) + pow20(e11);
            }
        }
    }

    // Reduce across the 4 lanes sharing a row, stage per-warp_n, then combine
#pragma unroll
    for (int mt = 0; mt < 4; mt++)
#pragma unroll
        for (int h = 0; h < 2; h++) {
            float v1 = p1r[mt][h], v2 = p2r[mt][h];
            v1 += __shfl_xor_sync(0xffffffffu, v1, 1);
            v1 += __shfl_xor_sync(0xffffffffu, v1, 2);
            v2 += __shfl_xor_sync(0xffffffffu, v2, 1);
            v2 += __shfl_xor_sync(0xffffffffu, v2, 2);
            if (q == 0) {
                int lr = warp_m * 64 + mt * 16 + h * 8 + g;
                s1w[warp_n * 128 + lr] = v1;
                s2w[warp_n * 128 + lr] = v2;
            }
        }
    __syncthreads();
    if (tid < 128) {
        float t1 = s1w[tid] + s1w[128 + tid] + s1w[256 + tid] + s1w[384 + tid];
        float t2 = s2w[tid] + s2w[128 + tid] + s2w[256 + tid] + s2w[384 + tid];
        g_ps1[(size_t)(rowBase + tid) * NT + bx] = t1;
        g_ps2[(size_t)(rowBase + tid) * NT + bx] = t2;
    }
}

__device__ __forceinline__ float blkred128(float v, float* sh) {
    int t = threadIdx.x;
    sh[t] = v;
    __syncthreads();
#pragma unroll
    for (int o = 64; o > 0; o >>= 1) {
        if (t < o) sh[t] += sh[t + o];
        __syncthreads();
    }
    float r = sh[0];
    __syncthreads();
    return r;
}

// Per-row: reduce partials, label logit + margin, row loss term, 1/sum(exp)
__global__ void rowfinal_kernel(const float* __restrict__ X, const float* __restrict__ Wt,
                                const float* __restrict__ bias, const int* __restrict__ labels) {
    __shared__ float sh[128];
    int row = blockIdx.x, t = threadIdx.x;

    float s1 = 0.f, s2 = 0.f;
    for (int j = t; j < NT; j += 128) {
        s1 += g_ps1[(size_t)row * NT + j];
        s2 += g_ps2[(size_t)row * NT + j];
    }
    int lab = labels[row];
    float d = X[(size_t)row * D_ + t] * Wt[(size_t)lab * D_ + t];

    s1 = blkred128(s1, sh);
    s2 = blkred128(s2, sh);
    d  = blkred128(d, sh);

    if (t == 0) {
        float wl = fmaf(d * g_invx[row], g_invw[lab], bias[lab]);
        float c = fminf(fmaxf(wl, -1.f + 1e-7f), 1.f - 1e-7f);
        // cos(acos(c) + M) = c*cos(M) - sqrt(1-c^2)*sin(M),  M = 0.1
        float cosm = c * 0.9950041652780258f
                   - sqrtf(fmaxf(1.f - c * c, 0.f)) * 0.09983341664682815f;
        float e2l = pow20(__expf(wl));
        float e2m = pow20(__expf(cosm));
        float s2p = s2 - e2l + e2m;
        g_rowloss[row] = logf(s2p) - 20.f * cosm;   // -logp[label]
        g_invs1[row] = 1.f / s1;
    }
}

__global__ void loss_kernel(float* __restrict__ out, int out_size) {
    __shared__ float sh[256];
    int t = threadIdx.x;
    float s = 0.f;
    for (int i = t; i < B_; i += 256) s += g_rowloss[i];
    sh[t] = s;
    __syncthreads();
#pragma unroll
    for (int o = 128; o > 0; o >>= 1) {
        if (t < o) sh[t] += sh[t + o];
        __syncthreads();
    }
    if (t == 0) out[out_size - 1] = sh[0] / (float)B_;
}

// prediction = exp(wf) / sum(exp(wf)) ; float4 in-place scale
__global__ void scale_kernel(float* __restrict__ out) {
    int row = blockIdx.y;
    float inv = g_invs1[row];
    int i = blockIdx.x * blockDim.x + threadIdx.x;   // float4 index, C_/4 = 12500
    if (i < C_ / 4) {
        float4* p = (float4*)(out + (size_t)row * C_);
        float4 v = p[i];
        v.x *= inv; v.y *= inv; v.z *= inv; v.w *= inv;
        p[i] = v;
    }
}

extern "C" void kernel_launch(void* const* d_in, const int* in_sizes, int n_in,
                              void* d_out, int out_size) {
    const float* X      = (const float*)d_in[0];   // [2048, 128]
    const float* W      = (const float*)d_in[1];   // [50000, 128]
    const float* bias   = (const float*)d_in[2];   // [50000]
    const int*   labels = (const int*)d_in[3];     // [2048]
    float* out = (float*)d_out;                    // [2048*50000 + 1]
    (void)in_sizes; (void)n_in;

    const int SMEM_BYTES = (2 * 128 * LDA + 3 * 128 + 2 * 512) * 4;  // 140800
    cudaFuncSetAttribute(gemm_tc_kernel,
                         cudaFuncAttributeMaxDynamicSharedMemorySize, SMEM_BYTES);

    rownorm_kernel<<<B_ / 8, 256>>>(X, B_, 0);
    rownorm_kernel<<<(C_ + 7) / 8, 256>>>(W, C_, 1);
    gemm_tc_kernel<<<dim3(NT, B_ / BM), 256, SMEM_BYTES>>>(X, W, bias, out);
    rowfinal_kernel<<<B_, 128>>>(X, W, bias, labels);
    loss_kernel<<<1, 256>>>(out, out_size);
    scale_kernel<<<dim3((C_ / 4 + 255) / 256, B_), 256>>>(out);
}

// round 6
// speedup vs baseline: 2.3761x; 1.1357x over previous
#include <cuda_runtime.h>
#include <cstdint>

// Problem constants
#define B_ 2048
#define C_ 50000
#define D_ 128
#define BM 128
#define BN 128
#define NT ((C_ + BN - 1) / BN)   /* 391 */
#define LDA 132                   /* padded smem row stride (floats) */
#define NCTA_PER_ROW 9            /* persistent CTAs per M-block */
#define TILES_PER_CTA ((NT + NCTA_PER_ROW - 1) / NCTA_PER_ROW)  /* 44 */

// Scratch (static device arrays: allocation-free per harness rules)
__device__ float g_invx[B_];
__device__ float g_invw[C_];
__device__ float g_ps1[(size_t)B_ * NT];
__device__ float g_ps2[(size_t)B_ * NT];
__device__ float g_rowloss[B_];
__device__ float g_invs1[B_];

// ---------------- helpers ----------------
__device__ __forceinline__ uint32_t smem_u32(const void* p) {
    uint32_t a;
    asm("{ .reg .u64 t; cvta.to.shared.u64 t, %1; cvt.u32.u64 %0, t; }"
        : "=r"(a) : "l"(p));
    return a;
}

__device__ __forceinline__ void cpasync16(uint32_t dst, const void* src, int sz) {
    asm volatile("cp.async.cg.shared.global [%0], [%1], 16, %2;"
                 :: "r"(dst), "l"(src), "r"(sz));
}

// tf32 mma m16n8k8 (portable sm_80+ ISA)
__device__ __forceinline__ void mma_tf32(float* c, const uint32_t* a, const uint32_t* b) {
    asm volatile(
        "mma.sync.aligned.m16n8k8.row.col.f32.tf32.tf32.f32 "
        "{%0,%1,%2,%3}, {%4,%5,%6,%7}, {%8,%9}, {%0,%1,%2,%3};"
        : "+f"(c[0]), "+f"(c[1]), "+f"(c[2]), "+f"(c[3])
        : "r"(a[0]), "r"(a[1]), "r"(a[2]), "r"(a[3]), "r"(b[0]), "r"(b[1]));
}

// e^20 via 5 multiplies
__device__ __forceinline__ float pow20(float e) {
    float t2 = e * e;
    float t4 = t2 * t2;
    float t8 = t4 * t4;
    float t16 = t8 * t8;
    return t16 * t4;
}

// ---------------- kernels ----------------

// 1 / max(||row||, 1e-12) ; one warp per row, D=128
__global__ void rownorm_kernel(const float* __restrict__ v, int nrows, int mode) {
    int row = blockIdx.x * 8 + (threadIdx.x >> 5);
    if (row >= nrows) return;
    int lane = threadIdx.x & 31;
    float4 q = *(const float4*)(v + (size_t)row * D_ + lane * 4);
    float s = q.x * q.x + q.y * q.y + q.z * q.z + q.w * q.w;
#pragma unroll
    for (int o = 16; o; o >>= 1) s += __shfl_xor_sync(0xffffffffu, s, o);
    if (lane == 0) {
        float r = 1.0f / fmaxf(sqrtf(s), 1e-12f);
        if (mode) g_invw[row] = r;
        else      g_invx[row] = r;
    }
}

// Persistent tensor-core GEMM with double-buffered B tiles.
// Each CTA: fixed M-block (by), range of N-tiles. A tile loaded once;
// B tile i+1 streams in via cp.async while tile i computes.
// Epilogue: wf = acc*invw*invx + bias; out = exp(wf) (streaming store);
// per-(row, N-tile) partial sums of exp and exp^20 to scratch.
// Dynamic smem: As[128*132] Bs0[128*132] Bs1[128*132] s1w[512] s2w[512]
__global__ __launch_bounds__(256, 1)
void gemm_tc_kernel(const float* __restrict__ X, const float* __restrict__ Wt,
                    const float* __restrict__ bias, float* __restrict__ out) {
    extern __shared__ __align__(16) float sm[];
    float* As  = sm;                       // 128*132
    float* Bs0 = sm + 128 * LDA;
    float* Bs1 = sm + 2 * 128 * LDA;
    float* s1w = sm + 3 * 128 * LDA;       // [4][128]
    float* s2w = s1w + 512;                // [4][128]

    const int tid  = threadIdx.x;
    const int w    = tid >> 5;
    const int lane = tid & 31;
    const int g    = lane >> 2;            // 0..7
    const int q    = lane & 3;             // 0..3
    const int warp_m = w >> 2;             // 0..1
    const int warp_n = w & 3;              // 0..3
    const int by = blockIdx.y;             // M block
    const int rowBase = by * BM;
    const int bx0 = blockIdx.x * TILES_PER_CTA;
    const int bx1 = min(NT, bx0 + TILES_PER_CTA);

    const uint32_t smA  = smem_u32(As);
    const uint32_t smB[2] = { smem_u32(Bs0), smem_u32(Bs1) };

    // Per-thread row indices / invx (fixed for the whole CTA)
    float invx_r[4][2];
#pragma unroll
    for (int mt = 0; mt < 4; mt++) {
        int lr = warp_m * 64 + mt * 16 + g;
        invx_r[mt][0] = g_invx[rowBase + lr];
        invx_r[mt][1] = g_invx[rowBase + lr + 8];
    }

    // Prologue: A tile + first B tile into buffer 0
    const float* Abase = X + (size_t)rowBase * D_;
#pragma unroll
    for (int i = 0; i < 16; i++) {
        int flat = tid + i * 256;
        int r = flat >> 5, c4 = flat & 31;
        cpasync16(smA + (uint32_t)(r * LDA + c4 * 4) * 4u,
                  Abase + (size_t)r * D_ + c4 * 4, 16);
    }
    {
        int colBase = bx0 * BN;
#pragma unroll
        for (int i = 0; i < 16; i++) {
            int flat = tid + i * 256;
            int r = flat >> 5, c4 = flat & 31;
            int gj = colBase + r;
            int ok = (gj < C_);
            cpasync16(smB[0] + (uint32_t)(r * LDA + c4 * 4) * 4u,
                      Wt + (size_t)(ok ? gj : 0) * D_ + c4 * 4, ok ? 16 : 0);
        }
    }
    asm volatile("cp.async.commit_group;" ::: "memory");
    asm volatile("cp.async.wait_group 0;" ::: "memory");
    __syncthreads();

    const float* Aw0 = As + (warp_m * 64 + g) * LDA + q;

    for (int it = 0; it < bx1 - bx0; it++) {
        const int bx = bx0 + it;
        const int colBase = bx * BN;
        const float* Bcur = (it & 1) ? Bs1 : Bs0;
        const uint32_t smBnext = smB[(it & 1) ^ 1];

        // Kick off next B tile load (overlaps with this tile's compute)
        if (it + 1 < bx1 - bx0) {
            int nb = (bx + 1) * BN;
#pragma unroll
            for (int i = 0; i < 16; i++) {
                int flat = tid + i * 256;
                int r = flat >> 5, c4 = flat & 31;
                int gj = nb + r;
                int ok = (gj < C_);
                cpasync16(smBnext + (uint32_t)(r * LDA + c4 * 4) * 4u,
                          Wt + (size_t)(ok ? gj : 0) * D_ + c4 * 4, ok ? 16 : 0);
            }
            asm volatile("cp.async.commit_group;" ::: "memory");
        }

        // MMA mainloop: warp tile 64x32 = 4x4 m16n8k8, K in 16 steps
        float acc[4][4][4];
#pragma unroll
        for (int mt = 0; mt < 4; mt++)
#pragma unroll
            for (int nt = 0; nt < 4; nt++)
#pragma unroll
                for (int r = 0; r < 4; r++) acc[mt][nt][r] = 0.f;

        const float* Bw = Bcur + (warp_n * 32 + g) * LDA + q;
#pragma unroll
        for (int ks = 0; ks < 16; ks++) {
            const int kb = ks * 8;
            uint32_t af[4][4], bf[4][2];
#pragma unroll
            for (int mt = 0; mt < 4; mt++) {
                const float* ap = Aw0 + mt * 16 * LDA + kb;
                af[mt][0] = __float_as_uint(ap[0]);
                af[mt][1] = __float_as_uint(ap[8 * LDA]);
                af[mt][2] = __float_as_uint(ap[4]);
                af[mt][3] = __float_as_uint(ap[8 * LDA + 4]);
            }
#pragma unroll
            for (int nt = 0; nt < 4; nt++) {
                const float* bp = Bw + nt * 8 * LDA + kb;
                bf[nt][0] = __float_as_uint(bp[0]);
                bf[nt][1] = __float_as_uint(bp[4]);
            }
#pragma unroll
            for (int mt = 0; mt < 4; mt++)
#pragma unroll
                for (int nt = 0; nt < 4; nt++)
                    mma_tf32(acc[mt][nt], af[mt], bf[nt]);
        }

        // Epilogue: exp + streaming store + partial sums
        float p1r[4][2], p2r[4][2];
#pragma unroll
        for (int mt = 0; mt < 4; mt++) {
            p1r[mt][0] = p1r[mt][1] = 0.f;
            p2r[mt][0] = p2r[mt][1] = 0.f;
        }

        // Per-thread column params (same for all mt; L2-hot loads)
        float iw0v[4], iw1v[4], bs0v[4], bs1v[4];
        bool validv[4];
#pragma unroll
        for (int nt = 0; nt < 4; nt++) {
            int cg = colBase + warp_n * 32 + nt * 8;
            int lc = cg + 2 * q;
            bool valid = cg < C_;
            validv[nt] = valid;
            iw0v[nt] = valid ? g_invw[lc]     : 0.f;
            iw1v[nt] = valid ? g_invw[lc + 1] : 0.f;
            bs0v[nt] = valid ? bias[lc]       : 0.f;
            bs1v[nt] = valid ? bias[lc + 1]   : 0.f;
        }

#pragma unroll
        for (int mt = 0; mt < 4; mt++) {
            const int lr0 = warp_m * 64 + mt * 16 + g;
            const float inx0 = invx_r[mt][0];
            const float inx1 = invx_r[mt][1];
            float* out0 = out + (size_t)(rowBase + lr0) * C_ + colBase;
            float* out1 = out + (size_t)(rowBase + lr0 + 8) * C_ + colBase;
#pragma unroll
            for (int nt = 0; nt < 4; nt++) {
                const int lc = warp_n * 32 + nt * 8 + 2 * q;
                float e00 = __expf(fmaf(acc[mt][nt][0] * iw0v[nt], inx0, bs0v[nt]));
                float e01 = __expf(fmaf(acc[mt][nt][1] * iw1v[nt], inx0, bs1v[nt]));
                float e10 = __expf(fmaf(acc[mt][nt][2] * iw0v[nt], inx1, bs0v[nt]));
                float e11 = __expf(fmaf(acc[mt][nt][3] * iw1v[nt], inx1, bs1v[nt]));
                if (validv[nt]) {
                    __stcs((float2*)(out0 + lc), make_float2(e00, e01));
                    __stcs((float2*)(out1 + lc), make_float2(e10, e11));
                    p1r[mt][0] += e00 + e01;
                    p1r[mt][1] += e10 + e11;
                    p2r[mt][0] += pow20(e00) + pow20(e01);
                    p2r[mt][1] += pow20(e10) + pow20(e11);
                }
            }
        }

        // Reduce across 4 lanes sharing a row, stage per warp_n
#pragma unroll
        for (int mt = 0; mt < 4; mt++)
#pragma unroll
            for (int h = 0; h < 2; h++) {
                float v1 = p1r[mt][h], v2 = p2r[mt][h];
                v1 += __shfl_xor_sync(0xffffffffu, v1, 1);
                v1 += __shfl_xor_sync(0xffffffffu, v1, 2);
                v2 += __shfl_xor_sync(0xffffffffu, v2, 1);
                v2 += __shfl_xor_sync(0xffffffffu, v2, 2);
                if (q == 0) {
                    int lr = warp_m * 64 + mt * 16 + h * 8 + g;
                    s1w[warp_n * 128 + lr] = v1;
                    s2w[warp_n * 128 + lr] = v2;
                }
            }
        __syncthreads();
        if (tid < 128) {
            float t1 = s1w[tid] + s1w[128 + tid] + s1w[256 + tid] + s1w[384 + tid];
            float t2 = s2w[tid] + s2w[128 + tid] + s2w[256 + tid] + s2w[384 + tid];
            g_ps1[(size_t)(rowBase + tid) * NT + bx] = t1;
            g_ps2[(size_t)(rowBase + tid) * NT + bx] = t2;
        }
        // Next tile's load must be complete; also protects s1w reuse
        asm volatile("cp.async.wait_group 0;" ::: "memory");
        __syncthreads();
    }
}

__device__ __forceinline__ float blkred128(float v, float* sh) {
    int t = threadIdx.x;
    sh[t] = v;
    __syncthreads();
#pragma unroll
    for (int o = 64; o > 0; o >>= 1) {
        if (t < o) sh[t] += sh[t + o];
        __syncthreads();
    }
    float r = sh[0];
    __syncthreads();
    return r;
}

// Per-row: reduce partials, label logit + margin, row loss term, 1/sum(exp)
__global__ void rowfinal_kernel(const float* __restrict__ X, const float* __restrict__ Wt,
                                const float* __restrict__ bias, const int* __restrict__ labels) {
    __shared__ float sh[128];
    int row = blockIdx.x, t = threadIdx.x;

    float s1 = 0.f, s2 = 0.f;
    for (int j = t; j < NT; j += 128) {
        s1 += g_ps1[(size_t)row * NT + j];
        s2 += g_ps2[(size_t)row * NT + j];
    }
    int lab = labels[row];
    float d = X[(size_t)row * D_ + t] * Wt[(size_t)lab * D_ + t];

    s1 = blkred128(s1, sh);
    s2 = blkred128(s2, sh);
    d  = blkred128(d, sh);

    if (t == 0) {
        float wl = fmaf(d * g_invx[row], g_invw[lab], bias[lab]);
        float c = fminf(fmaxf(wl, -1.f + 1e-7f), 1.f - 1e-7f);
        // cos(acos(c) + M) = c*cos(M) - sqrt(1-c^2)*sin(M),  M = 0.1
        float cosm = c * 0.9950041652780258f
                   - sqrtf(fmaxf(1.f - c * c, 0.f)) * 0.09983341664682815f;
        float e2l = pow20(__expf(wl));
        float e2m = pow20(__expf(cosm));
        float s2p = s2 - e2l + e2m;
        g_rowloss[row] = logf(s2p) - 20.f * cosm;   // -logp[label]
        g_invs1[row] = 1.f / s1;
    }
}

__global__ void loss_kernel(float* __restrict__ out, int out_size) {
    __shared__ float sh[256];
    int t = threadIdx.x;
    float s = 0.f;
    for (int i = t; i < B_; i += 256) s += g_rowloss[i];
    sh[t] = s;
    __syncthreads();
#pragma unroll
    for (int o = 128; o > 0; o >>= 1) {
        if (t < o) sh[t] += sh[t + o];
        __syncthreads();
    }
    if (t == 0) out[out_size - 1] = sh[0] / (float)B_;
}

// prediction = exp(wf) / sum(exp(wf)) ; streaming float4 in-place scale
__global__ void scale_kernel(float* __restrict__ out) {
    int row = blockIdx.y;
    float inv = g_invs1[row];
    int i = blockIdx.x * blockDim.x + threadIdx.x;   // float4 index, C_/4 = 12500
    if (i < C_ / 4) {
        float4* p = (float4*)(out + (size_t)row * C_);
        float4 v = __ldcs(p + i);
        v.x *= inv; v.y *= inv; v.z *= inv; v.w *= inv;
        __stcs(p + i, v);
    }
}

extern "C" void kernel_launch(void* const* d_in, const int* in_sizes, int n_in,
                              void* d_out, int out_size) {
    const float* X      = (const float*)d_in[0];   // [2048, 128]
    const float* W      = (const float*)d_in[1];   // [50000, 128]
    const float* bias   = (const float*)d_in[2];   // [50000]
    const int*   labels = (const int*)d_in[3];     // [2048]
    float* out = (float*)d_out;                    // [2048*50000 + 1]
    (void)in_sizes; (void)n_in;

    const int SMEM_BYTES = (3 * 128 * LDA + 2 * 512) * 4;   // 206848
    cudaFuncSetAttribute(gemm_tc_kernel,
                         cudaFuncAttributeMaxDynamicSharedMemorySize, SMEM_BYTES);

    rownorm_kernel<<<B_ / 8, 256>>>(X, B_, 0);
    rownorm_kernel<<<(C_ + 7) / 8, 256>>>(W, C_, 1);
    gemm_tc_kernel<<<dim3(NCTA_PER_ROW, B_ / BM), 256, SMEM_BYTES>>>(X, W, bias, out);
    rowfinal_kernel<<<B_, 128>>>(X, W, bias, labels);
    loss_kernel<<<1, 256>>>(out, out_size);
    scale_kernel<<<dim3((C_ / 4 + 255) / 256, B_), 256>>>(out);
}

// round 7
// speedup vs baseline: 2.3786x; 1.0010x over previous
#include <cuda_runtime.h>
#include <cstdint>

// Problem constants
#define B_ 2048
#define C_ 50000
#define D_ 128
#define BM 128
#define BN 128
#define NT ((C_ + BN - 1) / BN)   /* 391 */
#define LDA 132                   /* padded smem row stride (floats) */
#define NCTA_PER_ROW 9            /* persistent CTAs per M-block */
#define TILES_PER_CTA ((NT + NCTA_PER_ROW - 1) / NCTA_PER_ROW)  /* 44 */
#define NCH 49                    /* scale-kernel chunks per row: ceil(12500/256) */

// Scratch (static device arrays: allocation-free per harness rules)
__device__ float g_invx[B_];
__device__ float g_invw[C_];
__device__ float g_ps1[(size_t)B_ * NT];
__device__ float g_ps2b[(size_t)B_ * NCH];
__device__ float g_rowloss[B_];
__device__ float g_invs1[B_];

// ---------------- helpers ----------------
__device__ __forceinline__ uint32_t smem_u32(const void* p) {
    uint32_t a;
    asm("{ .reg .u64 t; cvta.to.shared.u64 t, %1; cvt.u32.u64 %0, t; }"
        : "=r"(a) : "l"(p));
    return a;
}

__device__ __forceinline__ void cpasync16(uint32_t dst, const void* src, int sz) {
    asm volatile("cp.async.cg.shared.global [%0], [%1], 16, %2;"
                 :: "r"(dst), "l"(src), "r"(sz));
}

// tf32 mma m16n8k8 (portable sm_80+ ISA)
__device__ __forceinline__ void mma_tf32(float* c, const uint32_t* a, const uint32_t* b) {
    asm volatile(
        "mma.sync.aligned.m16n8k8.row.col.f32.tf32.tf32.f32 "
        "{%0,%1,%2,%3}, {%4,%5,%6,%7}, {%8,%9}, {%0,%1,%2,%3};"
        : "+f"(c[0]), "+f"(c[1]), "+f"(c[2]), "+f"(c[3])
        : "r"(a[0]), "r"(a[1]), "r"(a[2]), "r"(a[3]), "r"(b[0]), "r"(b[1]));
}

// e^20 via 5 multiplies
__device__ __forceinline__ float pow20(float e) {
    float t2 = e * e;
    float t4 = t2 * t2;
    float t8 = t4 * t4;
    float t16 = t8 * t8;
    return t16 * t4;
}

// ---------------- kernels ----------------

// 1 / max(||row||, 1e-12) ; one warp per row, D=128
__global__ void rownorm_kernel(const float* __restrict__ v, int nrows, int mode) {
    int row = blockIdx.x * 8 + (threadIdx.x >> 5);
    if (row >= nrows) return;
    int lane = threadIdx.x & 31;
    float4 q = *(const float4*)(v + (size_t)row * D_ + lane * 4);
    float s = q.x * q.x + q.y * q.y + q.z * q.z + q.w * q.w;
#pragma unroll
    for (int o = 16; o; o >>= 1) s += __shfl_xor_sync(0xffffffffu, s, o);
    if (lane == 0) {
        float r = 1.0f / fmaxf(sqrtf(s), 1e-12f);
        if (mode) g_invw[row] = r;
        else      g_invx[row] = r;
    }
}

// Persistent tensor-core GEMM, double-buffered B. Epilogue computes e1 =
// exp(wf), streams it out, and accumulates ONLY sum(e1) per row (the
// exp^20 sum moved to the memory-bound scale pass).
// Dynamic smem: As[128*132] Bs0[128*132] Bs1[128*132] s1w[512]
__global__ __launch_bounds__(256, 1)
void gemm_tc_kernel(const float* __restrict__ X, const float* __restrict__ Wt,
                    const float* __restrict__ bias, float* __restrict__ out) {
    extern __shared__ __align__(16) float sm[];
    float* As  = sm;                       // 128*132
    float* Bs0 = sm + 128 * LDA;
    float* Bs1 = sm + 2 * 128 * LDA;
    float* s1w = sm + 3 * 128 * LDA;       // [4][128]

    const int tid  = threadIdx.x;
    const int w    = tid >> 5;
    const int lane = tid & 31;
    const int g    = lane >> 2;            // 0..7
    const int q    = lane & 3;             // 0..3
    const int warp_m = w >> 2;             // 0..1
    const int warp_n = w & 3;              // 0..3
    const int by = blockIdx.y;             // M block
    const int rowBase = by * BM;
    const int bx0 = blockIdx.x * TILES_PER_CTA;
    const int bx1 = min(NT, bx0 + TILES_PER_CTA);

    const uint32_t smA  = smem_u32(As);
    const uint32_t smB[2] = { smem_u32(Bs0), smem_u32(Bs1) };

    // Per-thread invx (fixed for the whole CTA)
    float invx_r[4][2];
#pragma unroll
    for (int mt = 0; mt < 4; mt++) {
        int lr = warp_m * 64 + mt * 16 + g;
        invx_r[mt][0] = g_invx[rowBase + lr];
        invx_r[mt][1] = g_invx[rowBase + lr + 8];
    }

    // Prologue: A tile + first B tile into buffer 0
    const float* Abase = X + (size_t)rowBase * D_;
#pragma unroll
    for (int i = 0; i < 16; i++) {
        int flat = tid + i * 256;
        int r = flat >> 5, c4 = flat & 31;
        cpasync16(smA + (uint32_t)(r * LDA + c4 * 4) * 4u,
                  Abase + (size_t)r * D_ + c4 * 4, 16);
    }
    {
        int colBase = bx0 * BN;
#pragma unroll
        for (int i = 0; i < 16; i++) {
            int flat = tid + i * 256;
            int r = flat >> 5, c4 = flat & 31;
            int gj = colBase + r;
            int ok = (gj < C_);
            cpasync16(smB[0] + (uint32_t)(r * LDA + c4 * 4) * 4u,
                      Wt + (size_t)(ok ? gj : 0) * D_ + c4 * 4, ok ? 16 : 0);
        }
    }
    asm volatile("cp.async.commit_group;" ::: "memory");
    asm volatile("cp.async.wait_group 0;" ::: "memory");
    __syncthreads();

    const float* Aw0 = As + (warp_m * 64 + g) * LDA + q;

    for (int it = 0; it < bx1 - bx0; it++) {
        const int bx = bx0 + it;
        const int colBase = bx * BN;
        const float* Bcur = (it & 1) ? Bs1 : Bs0;
        const uint32_t smBnext = smB[(it & 1) ^ 1];

        // Kick off next B tile load (overlaps with this tile's compute)
        if (it + 1 < bx1 - bx0) {
            int nb = (bx + 1) * BN;
#pragma unroll
            for (int i = 0; i < 16; i++) {
                int flat = tid + i * 256;
                int r = flat >> 5, c4 = flat & 31;
                int gj = nb + r;
                int ok = (gj < C_);
                cpasync16(smBnext + (uint32_t)(r * LDA + c4 * 4) * 4u,
                          Wt + (size_t)(ok ? gj : 0) * D_ + c4 * 4, ok ? 16 : 0);
            }
            asm volatile("cp.async.commit_group;" ::: "memory");
        }

        // MMA mainloop: warp tile 64x32 = 4x4 m16n8k8, K in 16 steps
        float acc[4][4][4];
#pragma unroll
        for (int mt = 0; mt < 4; mt++)
#pragma unroll
            for (int nt = 0; nt < 4; nt++)
#pragma unroll
                for (int r = 0; r < 4; r++) acc[mt][nt][r] = 0.f;

        const float* Bw = Bcur + (warp_n * 32 + g) * LDA + q;
#pragma unroll
        for (int ks = 0; ks < 16; ks++) {
            const int kb = ks * 8;
            uint32_t af[4][4], bf[4][2];
#pragma unroll
            for (int mt = 0; mt < 4; mt++) {
                const float* ap = Aw0 + mt * 16 * LDA + kb;
                af[mt][0] = __float_as_uint(ap[0]);
                af[mt][1] = __float_as_uint(ap[8 * LDA]);
                af[mt][2] = __float_as_uint(ap[4]);
                af[mt][3] = __float_as_uint(ap[8 * LDA + 4]);
            }
#pragma unroll
            for (int nt = 0; nt < 4; nt++) {
                const float* bp = Bw + nt * 8 * LDA + kb;
                bf[nt][0] = __float_as_uint(bp[0]);
                bf[nt][1] = __float_as_uint(bp[4]);
            }
#pragma unroll
            for (int mt = 0; mt < 4; mt++)
#pragma unroll
                for (int nt = 0; nt < 4; nt++)
                    mma_tf32(acc[mt][nt], af[mt], bf[nt]);
        }

        // Epilogue: exp + streaming store + sum(e1) only
        float p1r[4][2];
#pragma unroll
        for (int mt = 0; mt < 4; mt++) { p1r[mt][0] = p1r[mt][1] = 0.f; }

        float iw0v[4], iw1v[4], bs0v[4], bs1v[4];
        bool validv[4];
#pragma unroll
        for (int nt = 0; nt < 4; nt++) {
            int cg = colBase + warp_n * 32 + nt * 8;
            int lc = cg + 2 * q;
            bool valid = cg < C_;
            validv[nt] = valid;
            iw0v[nt] = valid ? g_invw[lc]     : 0.f;
            iw1v[nt] = valid ? g_invw[lc + 1] : 0.f;
            bs0v[nt] = valid ? bias[lc]       : 0.f;
            bs1v[nt] = valid ? bias[lc + 1]   : 0.f;
        }

#pragma unroll
        for (int mt = 0; mt < 4; mt++) {
            const int lr0 = warp_m * 64 + mt * 16 + g;
            const float inx0 = invx_r[mt][0];
            const float inx1 = invx_r[mt][1];
            float* out0 = out + (size_t)(rowBase + lr0) * C_ + colBase;
            float* out1 = out + (size_t)(rowBase + lr0 + 8) * C_ + colBase;
#pragma unroll
            for (int nt = 0; nt < 4; nt++) {
                const int lc = warp_n * 32 + nt * 8 + 2 * q;
                float e00 = __expf(fmaf(acc[mt][nt][0] * iw0v[nt], inx0, bs0v[nt]));
                float e01 = __expf(fmaf(acc[mt][nt][1] * iw1v[nt], inx0, bs1v[nt]));
                float e10 = __expf(fmaf(acc[mt][nt][2] * iw0v[nt], inx1, bs0v[nt]));
                float e11 = __expf(fmaf(acc[mt][nt][3] * iw1v[nt], inx1, bs1v[nt]));
                if (validv[nt]) {
                    __stcs((float2*)(out0 + lc), make_float2(e00, e01));
                    __stcs((float2*)(out1 + lc), make_float2(e10, e11));
                    p1r[mt][0] += e00 + e01;
                    p1r[mt][1] += e10 + e11;
                }
            }
        }

        // Reduce across 4 lanes sharing a row, stage per warp_n
#pragma unroll
        for (int mt = 0; mt < 4; mt++)
#pragma unroll
            for (int h = 0; h < 2; h++) {
                float v1 = p1r[mt][h];
                v1 += __shfl_xor_sync(0xffffffffu, v1, 1);
                v1 += __shfl_xor_sync(0xffffffffu, v1, 2);
                if (q == 0) {
                    int lr = warp_m * 64 + mt * 16 + h * 8 + g;
                    s1w[warp_n * 128 + lr] = v1;
                }
            }
        __syncthreads();
        if (tid < 128) {
            float t1 = s1w[tid] + s1w[128 + tid] + s1w[256 + tid] + s1w[384 + tid];
            g_ps1[(size_t)(rowBase + tid) * NT + bx] = t1;
        }
        asm volatile("cp.async.wait_group 0;" ::: "memory");
        __syncthreads();
    }
}

__device__ __forceinline__ float blkred128(float v, float* sh) {
    int t = threadIdx.x;
    sh[t] = v;
    __syncthreads();
#pragma unroll
    for (int o = 64; o > 0; o >>= 1) {
        if (t < o) sh[t] += sh[t + o];
        __syncthreads();
    }
    float r = sh[0];
    __syncthreads();
    return r;
}

// Pre-scale: per-row 1/sum(exp) from GEMM partials
__global__ void rowfinal_a_kernel() {
    __shared__ float sh[128];
    int row = blockIdx.x, t = threadIdx.x;
    float s1 = 0.f;
    for (int j = t; j < NT; j += 128) s1 += g_ps1[(size_t)row * NT + j];
    s1 = blkred128(s1, sh);
    if (t == 0) g_invs1[row] = 1.f / s1;
}

// prediction = e1 / sum ; ALSO accumulates sum(e1^20) per chunk (free ALU
// under the DRAM stream). grid = (NCH, B_)
__global__ void scale_kernel(float* __restrict__ out) {
    __shared__ float sh[256];
    int row = blockIdx.y;
    int t = threadIdx.x;
    float inv = g_invs1[row];
    int i = blockIdx.x * 256 + t;            // float4 index, C_/4 = 12500
    float p2 = 0.f;
    if (i < C_ / 4) {
        float4* p = (float4*)(out + (size_t)row * C_);
        float4 v = __ldcs(p + i);
        p2 = pow20(v.x) + pow20(v.y) + pow20(v.z) + pow20(v.w);
        v.x *= inv; v.y *= inv; v.z *= inv; v.w *= inv;
        __stcs(p + i, v);
    }
    sh[t] = p2;
    __syncthreads();
#pragma unroll
    for (int o = 128; o > 0; o >>= 1) {
        if (t < o) sh[t] += sh[t + o];
        __syncthreads();
    }
    if (t == 0) g_ps2b[(size_t)row * NCH + blockIdx.x] = sh[0];
}

// Post-scale: label logit + margin + row loss term
__global__ void rowfinal_b_kernel(const float* __restrict__ X, const float* __restrict__ Wt,
                                  const float* __restrict__ bias, const int* __restrict__ labels) {
    __shared__ float sh[128];
    int row = blockIdx.x, t = threadIdx.x;

    float s2 = (t < NCH) ? g_ps2b[(size_t)row * NCH + t] : 0.f;
    int lab = labels[row];
    float d = X[(size_t)row * D_ + t] * Wt[(size_t)lab * D_ + t];

    s2 = blkred128(s2, sh);
    d  = blkred128(d, sh);

    if (t == 0) {
        float wl = fmaf(d * g_invx[row], g_invw[lab], bias[lab]);
        float c = fminf(fmaxf(wl, -1.f + 1e-7f), 1.f - 1e-7f);
        // cos(acos(c) + M) = c*cos(M) - sqrt(1-c^2)*sin(M),  M = 0.1
        float cosm = c * 0.9950041652780258f
                   - sqrtf(fmaxf(1.f - c * c, 0.f)) * 0.09983341664682815f;
        float e2l = pow20(__expf(wl));
        float e2m = pow20(__expf(cosm));
        float s2p = s2 - e2l + e2m;
        g_rowloss[row] = logf(s2p) - 20.f * cosm;   // -logp[label]
    }
}

__global__ void loss_kernel(float* __restrict__ out, int out_size) {
    __shared__ float sh[256];
    int t = threadIdx.x;
    float s = 0.f;
    for (int i = t; i < B_; i += 256) s += g_rowloss[i];
    sh[t] = s;
    __syncthreads();
#pragma unroll
    for (int o = 128; o > 0; o >>= 1) {
        if (t < o) sh[t] += sh[t + o];
        __syncthreads();
    }
    if (t == 0) out[out_size - 1] = sh[0] / (float)B_;
}

extern "C" void kernel_launch(void* const* d_in, const int* in_sizes, int n_in,
                              void* d_out, int out_size) {
    const float* X      = (const float*)d_in[0];   // [2048, 128]
    const float* W      = (const float*)d_in[1];   // [50000, 128]
    const float* bias   = (const float*)d_in[2];   // [50000]
    const int*   labels = (const int*)d_in[3];     // [2048]
    float* out = (float*)d_out;                    // [2048*50000 + 1]
    (void)in_sizes; (void)n_in;

    const int SMEM_BYTES = (3 * 128 * LDA + 512) * 4;   // 204800
    cudaFuncSetAttribute(gemm_tc_kernel,
                         cudaFuncAttributeMaxDynamicSharedMemorySize, SMEM_BYTES);

    rownorm_kernel<<<B_ / 8, 256>>>(X, B_, 0);
    rownorm_kernel<<<(C_ + 7) / 8, 256>>>(W, C_, 1);
    gemm_tc_kernel<<<dim3(NCTA_PER_ROW, B_ / BM), 256, SMEM_BYTES>>>(X, W, bias, out);
    rowfinal_a_kernel<<<B_, 128>>>();
    scale_kernel<<<dim3(NCH, B_), 256>>>(out);
    rowfinal_b_kernel<<<B_, 128>>>(X, W, bias, labels);
    loss_kernel<<<1, 256>>>(out, out_size);
}

// round 9
// speedup vs baseline: 3.6795x; 1.5469x over previous
#include <cuda_runtime.h>
#include <cuda_fp16.h>
#include <cstdint>

// Problem constants
#define B_ 2048
#define C_ 50000
#define D_ 128
#define BM 128
#define BN 128
#define NT 391                    /* ceil(C_/BN) */
#define NCTA 18                   /* CTAs per M-block row */
#define TPC 22                    /* tiles per CTA: 18*22 = 396 >= 391 */

// Scratch (static device arrays: allocation-free per harness rules)
__device__ float g_invx[B_];
__device__ float g_invw[C_];
__device__ float g_ps1[(size_t)B_ * NT];
__device__ float g_ps2[(size_t)B_ * NT];
__device__ float g_rowloss[B_];
__device__ float g_invs1[B_];
__device__ __half g_xh[(size_t)B_ * D_];     // normalized X, half
__device__ __half g_wh[(size_t)C_ * D_];     // normalized W, half
__device__ __half g_e1h[(size_t)B_ * C_];    // exp(wf) intermediate, half

// ---------------- helpers ----------------
__device__ __forceinline__ uint32_t smem_u32(const void* p) {
    uint32_t a;
    asm("{ .reg .u64 t; cvta.to.shared.u64 t, %1; cvt.u32.u64 %0, t; }"
        : "=r"(a) : "l"(p));
    return a;
}

__device__ __forceinline__ void cpasync16(uint32_t dst, const void* src, int sz) {
    asm volatile("cp.async.cg.shared.global [%0], [%1], 16, %2;"
                 :: "r"(dst), "l"(src), "r"(sz));
}

// Swizzled 16B-chunk offset within a 128x128 half tile (rows of 16 chunks).
// chunk index c XORed with (row & 7) -> conflict-free ldmatrix.
__device__ __forceinline__ uint32_t tilechunk(int r, int c) {
    return ((uint32_t)(r * 16 + (c ^ (r & 7)))) << 4;
}

__device__ __forceinline__ void ldsm4(uint32_t* r, uint32_t addr) {
    asm volatile("ldmatrix.sync.aligned.m8n8.x4.shared.b16 {%0,%1,%2,%3}, [%4];"
                 : "=r"(r[0]), "=r"(r[1]), "=r"(r[2]), "=r"(r[3]) : "r"(addr));
}

// fp16 mma m16n8k16, fp32 accumulate (portable sm_70+ ISA)
__device__ __forceinline__ void mma_f16(float* c, const uint32_t* a,
                                        uint32_t b0, uint32_t b1) {
    asm volatile(
        "mma.sync.aligned.m16n8k16.row.col.f32.f16.f16.f32 "
        "{%0,%1,%2,%3}, {%4,%5,%6,%7}, {%8,%9}, {%0,%1,%2,%3};"
        : "+f"(c[0]), "+f"(c[1]), "+f"(c[2]), "+f"(c[3])
        : "r"(a[0]), "r"(a[1]), "r"(a[2]), "r"(a[3]), "r"(b0), "r"(b1));
}

__device__ __forceinline__ void stcs_h2(__half* p, __half2 v) {
    uint32_t u = *reinterpret_cast<uint32_t*>(&v);
    asm volatile("st.global.cs.b32 [%0], %1;" :: "l"(p), "r"(u));
}

// e^20 via 5 multiplies
__device__ __forceinline__ float pow20(float e) {
    float t2 = e * e;
    float t4 = t2 * t2;
    float t8 = t4 * t4;
    float t16 = t8 * t8;
    return t16 * t4;
}

// ---------------- kernels ----------------

// Row L2-normalize + convert to half (normalization folded into the halves).
// One warp per row; also stores 1/max(||row||,1e-12).
__global__ void rownorm_kernel(const float* __restrict__ v, int nrows, int mode) {
    int row = blockIdx.x * 8 + (threadIdx.x >> 5);
    if (row >= nrows) return;
    int lane = threadIdx.x & 31;
    float4 q = *(const float4*)(v + (size_t)row * D_ + lane * 4);
    float s = q.x * q.x + q.y * q.y + q.z * q.z + q.w * q.w;
#pragma unroll
    for (int o = 16; o; o >>= 1) s += __shfl_xor_sync(0xffffffffu, s, o);
    float r = 1.0f / fmaxf(sqrtf(s), 1e-12f);
    __half* base = (mode ? g_wh : g_xh) + (size_t)row * D_ + lane * 4;
    ((__half2*)base)[0] = __floats2half2_rn(q.x * r, q.y * r);
    ((__half2*)base)[1] = __floats2half2_rn(q.z * r, q.w * r);
    if (lane == 0) {
        if (mode) g_invw[row] = r;
        else      g_invx[row] = r;
    }
}

// Persistent fp16 tensor-core GEMM (m16n8k16 + ldmatrix), double-buffered B.
// acc = Xn_tile @ Wn_tile^T (cosine); wf = acc + bias; e1 = exp(wf) -> half
// scratch; per-(row, N-tile) partial sums of e1 and e1^20.
// smem: A 32KB | B0 32KB | B1 32KB | s1w 2KB | s2w 2KB = 100KB
__global__ __launch_bounds__(256, 2)
void gemm_tc_kernel(const float* __restrict__ bias) {
    extern __shared__ __align__(128) char sm[];
    __half* As = (__half*)sm;
    float* s1w = (float*)(sm + 98304);      // [4][128]
    float* s2w = s1w + 512;                 // [4][128]

    const int tid  = threadIdx.x;
    const int w    = tid >> 5;
    const int lane = tid & 31;
    const int g    = lane >> 2;             // 0..7
    const int q    = lane & 3;              // 0..3
    const int warp_m = w >> 2;              // 0..1
    const int warp_n = w & 3;               // 0..3
    const int by = blockIdx.y;
    const int rowBase = by * BM;
    const int bx0 = blockIdx.x * TPC;
    const int bx1 = min(NT, bx0 + TPC);

    const uint32_t uA = smem_u32(As);
    const uint32_t uB[2] = { uA + 32768u, uA + 65536u };

    // ldmatrix per-thread address precompute
    const int l16 = lane & 15;
    const int lhi = lane >> 4;              // chunk-hi selector for A
    uint32_t baseA[4], xorA[4];
#pragma unroll
    for (int mt = 0; mt < 4; mt++) {
        int R = warp_m * 64 + mt * 16 + l16;
        baseA[mt] = uA + (uint32_t)R * 256u + (uint32_t)((lhi ^ (R & 1)) << 4);
        xorA[mt]  = (uint32_t)(R & 6) << 4;
    }
    const int bhi = (lane >> 3) & 1;        // chunk-hi selector for B
    const int bnt = (lane >> 4) & 1;        // nt selector within pair
    uint32_t baseBoff[2];
    const uint32_t xorB = (uint32_t)(lane & 6) << 4;
#pragma unroll
    for (int pr = 0; pr < 2; pr++) {
        int Rn = warp_n * 32 + pr * 16 + bnt * 8 + (lane & 7);
        baseBoff[pr] = (uint32_t)Rn * 256u + (uint32_t)((bhi ^ (Rn & 1)) << 4);
    }

    // Prologue: A tile (once) + first B tile into buffer 0
#pragma unroll
    for (int i = 0; i < 8; i++) {
        int flat = tid + i * 256;           // [0, 2048)
        int r = flat >> 4, c = flat & 15;
        cpasync16(uA + tilechunk(r, c),
                  g_xh + (size_t)(rowBase + r) * D_ + c * 8, 16);
    }
    {
        int colBase = bx0 * BN;
#pragma unroll
        for (int i = 0; i < 8; i++) {
            int flat = tid + i * 256;
            int r = flat >> 4, c = flat & 15;
            int gj = colBase + r;
            int ok = (gj < C_);
            cpasync16(uB[0] + tilechunk(r, c),
                      g_wh + (size_t)(ok ? gj : 0) * D_ + c * 8, ok ? 16 : 0);
        }
    }
    asm volatile("cp.async.commit_group;" ::: "memory");
    asm volatile("cp.async.wait_group 0;" ::: "memory");
    __syncthreads();

    for (int it = 0; it < bx1 - bx0; it++) {
        const int bx = bx0 + it;
        const int colBase = bx * BN;
        const uint32_t uBc = uB[it & 1];
        const uint32_t uBn = uB[(it & 1) ^ 1];

        // Stream next B tile while computing this one
        if (it + 1 < bx1 - bx0) {
            int nb = (bx + 1) * BN;
#pragma unroll
            for (int i = 0; i < 8; i++) {
                int flat = tid + i * 256;
                int r = flat >> 4, c = flat & 15;
                int gj = nb + r;
                int ok = (gj < C_);
                cpasync16(uBn + tilechunk(r, c),
                          g_wh + (size_t)(ok ? gj : 0) * D_ + c * 8, ok ? 16 : 0);
            }
            asm volatile("cp.async.commit_group;" ::: "memory");
        }

        // MMA mainloop: 8 k-steps of k=16; warp tile 64x32
        float acc[4][4][4];
#pragma unroll
        for (int mt = 0; mt < 4; mt++)
#pragma unroll
            for (int nt = 0; nt < 4; nt++)
#pragma unroll
                for (int r = 0; r < 4; r++) acc[mt][nt][r] = 0.f;

#pragma unroll
        for (int s = 0; s < 8; s++) {
            const uint32_t koff = (uint32_t)(2 * s) << 4;
            uint32_t af[4][4], bf[2][4];
#pragma unroll
            for (int mt = 0; mt < 4; mt++)
                ldsm4(af[mt], baseA[mt] + (koff ^ xorA[mt]));
#pragma unroll
            for (int pr = 0; pr < 2; pr++)
                ldsm4(bf[pr], uBc + baseBoff[pr] + (koff ^ xorB));
#pragma unroll
            for (int mt = 0; mt < 4; mt++)
#pragma unroll
                for (int pr = 0; pr < 2; pr++) {
                    mma_f16(acc[mt][pr * 2 + 0], af[mt], bf[pr][0], bf[pr][1]);
                    mma_f16(acc[mt][pr * 2 + 1], af[mt], bf[pr][2], bf[pr][3]);
                }
        }

        // Epilogue: wf = acc + bias; e1 = exp(wf); half store + partial sums
        float bs0v[4], bs1v[4];
        bool validv[4];
#pragma unroll
        for (int nt = 0; nt < 4; nt++) {
            int cg = colBase + warp_n * 32 + nt * 8;
            bool valid = cg < C_;
            validv[nt] = valid;
            bs0v[nt] = valid ? bias[cg + 2 * q]     : 0.f;
            bs1v[nt] = valid ? bias[cg + 2 * q + 1] : 0.f;
        }

        float p1r[4][2], p2r[4][2];
#pragma unroll
        for (int mt = 0; mt < 4; mt++) {
            p1r[mt][0] = p1r[mt][1] = 0.f;
            p2r[mt][0] = p2r[mt][1] = 0.f;
        }

#pragma unroll
        for (int mt = 0; mt < 4; mt++) {
            const int lr0 = warp_m * 64 + mt * 16 + g;
            __half* o0 = g_e1h + (size_t)(rowBase + lr0) * C_ + colBase;
            __half* o1 = g_e1h + (size_t)(rowBase + lr0 + 8) * C_ + colBase;
#pragma unroll
            for (int nt = 0; nt < 4; nt++) {
                const int nc = warp_n * 32 + nt * 8 + 2 * q;
                float e00 = __expf(acc[mt][nt][0] + bs0v[nt]);
                float e01 = __expf(acc[mt][nt][1] + bs1v[nt]);
                float e10 = __expf(acc[mt][nt][2] + bs0v[nt]);
                float e11 = __expf(acc[mt][nt][3] + bs1v[nt]);
                if (validv[nt]) {
                    stcs_h2(o0 + nc, __floats2half2_rn(e00, e01));
                    stcs_h2(o1 + nc, __floats2half2_rn(e10, e11));
                    p1r[mt][0] += e00 + e01;
                    p1r[mt][1] += e10 + e11;
                    p2r[mt][0] += pow20(e00) + pow20(e01);
                    p2r[mt][1] += pow20(e10) + pow20(e11);
                }
            }
        }

        // Reduce across 4 lanes sharing a row, stage per warp_n, combine
#pragma unroll
        for (int mt = 0; mt < 4; mt++)
#pragma unroll
            for (int h = 0; h < 2; h++) {
                float v1 = p1r[mt][h], v2 = p2r[mt][h];
                v1 += __shfl_xor_sync(0xffffffffu, v1, 1);
                v1 += __shfl_xor_sync(0xffffffffu, v1, 2);
                v2 += __shfl_xor_sync(0xffffffffu, v2, 1);
                v2 += __shfl_xor_sync(0xffffffffu, v2, 2);
                if (q == 0) {
                    int lr = warp_m * 64 + mt * 16 + h * 8 + g;
                    s1w[warp_n * 128 + lr] = v1;
                    s2w[warp_n * 128 + lr] = v2;
                }
            }
        __syncthreads();
        if (tid < 128) {
            float t1 = s1w[tid] + s1w[128 + tid] + s1w[256 + tid] + s1w[384 + tid];
            float t2 = s2w[tid] + s2w[128 + tid] + s2w[256 + tid] + s2w[384 + tid];
            g_ps1[(size_t)(rowBase + tid) * NT + bx] = t1;
            g_ps2[(size_t)(rowBase + tid) * NT + bx] = t2;
        }
        asm volatile("cp.async.wait_group 0;" ::: "memory");
        __syncthreads();
    }
}

__device__ __forceinline__ float blkred128(float v, float* sh) {
    int t = threadIdx.x;
    sh[t] = v;
    __syncthreads();
#pragma unroll
    for (int o = 64; o > 0; o >>= 1) {
        if (t < o) sh[t] += sh[t + o];
        __syncthreads();
    }
    float r = sh[0];
    __syncthreads();
    return r;
}

// Per-row: reduce partials, label logit + margin, row loss term, 1/sum(exp)
__global__ void rowfinal_kernel(const float* __restrict__ X, const float* __restrict__ Wt,
                                const float* __restrict__ bias, const int* __restrict__ labels) {
    __shared__ float sh[128];
    int row = blockIdx.x, t = threadIdx.x;

    float s1 = 0.f, s2 = 0.f;
    for (int j = t; j < NT; j += 128) {
        s1 += g_ps1[(size_t)row * NT + j];
        s2 += g_ps2[(size_t)row * NT + j];
    }
    int lab = labels[row];
    float d = X[(size_t)row * D_ + t] * Wt[(size_t)lab * D_ + t];

    s1 = blkred128(s1, sh);
    s2 = blkred128(s2, sh);
    d  = blkred128(d, sh);

    if (t == 0) {
        float wl = fmaf(d * g_invx[row], g_invw[lab], bias[lab]);
        float c = fminf(fmaxf(wl, -1.f + 1e-7f), 1.f - 1e-7f);
        // cos(acos(c) + M) = c*cos(M) - sqrt(1-c^2)*sin(M),  M = 0.1
        float cosm = c * 0.9950041652780258f
                   - sqrtf(fmaxf(1.f - c * c, 0.f)) * 0.09983341664682815f;
        float e2l = pow20(__expf(wl));
        float e2m = pow20(__expf(cosm));
        float s2p = s2 - e2l + e2m;
        g_rowloss[row] = logf(s2p) - 20.f * cosm;   // -logp[label]
        g_invs1[row] = 1.f / s1;
    }
}

__global__ void loss_kernel(float* __restrict__ out, int out_size) {
    __shared__ float sh[256];
    int t = threadIdx.x;
    float s = 0.f;
    for (int i = t; i < B_; i += 256) s += g_rowloss[i];
    sh[t] = s;
    __syncthreads();
#pragma unroll
    for (int o = 128; o > 0; o >>= 1) {
        if (t < o) sh[t] += sh[t + o];
        __syncthreads();
    }
    if (t == 0) out[out_size - 1] = sh[0] / (float)B_;
}

// prediction = half(e1) * invs1 -> float out. Reads 205MB, writes 410MB.
__global__ void scale_kernel(float* __restrict__ out) {
    int row = blockIdx.y;
    int idx = blockIdx.x * 256 + threadIdx.x;     // 8-half chunk, C_/8 = 6250
    if (idx >= C_ / 8) return;
    float inv = g_invs1[row];
    uint4 u = __ldcs((const uint4*)(g_e1h + (size_t)row * C_) + idx);
    float2 f0 = __half22float2(*(__half2*)&u.x);
    float2 f1 = __half22float2(*(__half2*)&u.y);
    float2 f2 = __half22float2(*(__half2*)&u.z);
    float2 f3 = __half22float2(*(__half2*)&u.w);
    float4 a = make_float4(f0.x * inv, f0.y * inv, f1.x * inv, f1.y * inv);
    float4 b = make_float4(f2.x * inv, f2.y * inv, f3.x * inv, f3.y * inv);
    float4* dst = (float4*)(out + (size_t)row * C_) + idx * 2;
    __stcs(dst, a);
    __stcs(dst + 1, b);
}

extern "C" void kernel_launch(void* const* d_in, const int* in_sizes, int n_in,
                              void* d_out, int out_size) {
    const float* X      = (const float*)d_in[0];   // [2048, 128]
    const float* W      = (const float*)d_in[1];   // [50000, 128]
    const float* bias   = (const float*)d_in[2];   // [50000]
    const int*   labels = (const int*)d_in[3];     // [2048]
    float* out = (float*)d_out;                    // [2048*50000 + 1]
    (void)in_sizes; (void)n_in;

    const int SMEM_BYTES = 102400;   // 100KB -> 2 CTAs/SM
    cudaFuncSetAttribute(gemm_tc_kernel,
                         cudaFuncAttributeMaxDynamicSharedMemorySize, SMEM_BYTES);

    rownorm_kernel<<<B_ / 8, 256>>>(X, B_, 0);
    rownorm_kernel<<<(C_ + 7) / 8, 256>>>(W, C_, 1);
    gemm_tc_kernel<<<dim3(NCTA, B_ / BM), 256, SMEM_BYTES>>>(bias);
    rowfinal_kernel<<<B_, 128>>>(X, W, bias, labels);
    scale_kernel<<<dim3((C_ / 8 + 255) / 256, B_), 256>>>(out);
    loss_kernel<<<1, 256>>>(out, out_size);
}